// round 9
// baseline (speedup 1.0000x reference)
#include <cuda_runtime.h>
#include <cuda_fp16.h>
#include <cstdint>

// Problem constants
#define B_ 8
#define S_ 1024
#define D_ 1024
#define M_TOT (B_ * S_)   // 8192

// Scratch (allocation-free rule: __device__ globals)
__device__ float  g_Q[B_ * S_ * D_];
__device__ float  g_K[B_ * S_ * D_];
__device__ float  g_V[B_ * S_ * D_];
__device__ __half g_q16[B_ * S_ * D_];
__device__ __half g_k16[B_ * S_ * D_];
__device__ __half g_v16[B_ * S_ * D_];
__device__ __half g_a16[B_ * S_ * D_];
__device__ __half g_wq16[D_ * D_];
__device__ __half g_wk16[D_ * D_];
__device__ __half g_wv16[D_ * D_];
__device__ __half g_wo16[D_ * D_];

// ---------------------------------------------------------------------------
// Helpers
// ---------------------------------------------------------------------------
__device__ __forceinline__ uint32_t smem_u32(const void* p) {
    uint32_t a;
    asm("{ .reg .u64 t; cvta.to.shared.u64 t, %1; cvt.u32.u64 %0, t; }"
        : "=r"(a) : "l"(p));
    return a;
}

#define LDSM4(r, addr)                                                        \
    asm volatile("ldmatrix.sync.aligned.m8n8.x4.shared.b16 "                  \
                 "{%0, %1, %2, %3}, [%4];"                                    \
                 : "=r"((r)[0]), "=r"((r)[1]), "=r"((r)[2]), "=r"((r)[3])     \
                 : "r"(addr))

#define MMA16816F16(d, a, b)                                                  \
    asm volatile("mma.sync.aligned.m16n8k16.row.col.f32.f16.f16.f32 "         \
                 "{%0, %1, %2, %3}, {%4, %5, %6, %7}, {%8, %9}, "             \
                 "{%0, %1, %2, %3};"                                          \
                 : "+f"((d)[0]), "+f"((d)[1]), "+f"((d)[2]), "+f"((d)[3])     \
                 : "r"((a)[0]), "r"((a)[1]), "r"((a)[2]), "r"((a)[3]),        \
                   "r"((b)[0]), "r"((b)[1]))

#define CP_ASYNC16(dst, src)                                                  \
    asm volatile("cp.async.cg.shared.global [%0], [%1], 16;"                  \
                 :: "r"(dst), "l"(src) : "memory")
#define CP_COMMIT() asm volatile("cp.async.commit_group;" ::: "memory")
#define CP_WAIT2()  asm volatile("cp.async.wait_group 2;" ::: "memory")

__device__ __forceinline__ uint32_t mapa_peer(uint32_t addr, uint32_t rank) {
    uint32_t r;
    asm("mapa.shared::cluster.u32 %0, %1, %2;" : "=r"(r) : "r"(addr), "r"(rank));
    return r;
}
__device__ __forceinline__ float ld_dsmem(uint32_t addr) {
    float v;
    asm volatile("ld.shared::cluster.f32 %0, [%1];" : "=f"(v) : "r"(addr));
    return v;
}
#define CLUSTER_SYNC() do {                                                   \
    asm volatile("barrier.cluster.arrive.aligned;" ::: "memory");             \
    asm volatile("barrier.cluster.wait.aligned;"   ::: "memory");             \
} while (0)

// ---------------------------------------------------------------------------
// fp32 -> fp16 pre-conversion (multi-tensor, z-indexed)
// ---------------------------------------------------------------------------
struct CvtArgs { const float4* in[4]; uint2* out[4]; };

__global__ void cvt_multi(CvtArgs a, int n4)
{
    const float4* in = a.in[blockIdx.z];
    uint2* out = a.out[blockIdx.z];
    int i = blockIdx.x * blockDim.x + threadIdx.x;
    if (i < n4) {
        float4 v = in[i];
        uint32_t p01, p23;
        asm("cvt.rn.f16x2.f32 %0, %1, %2;" : "=r"(p01) : "f"(v.y), "f"(v.x));
        asm("cvt.rn.f16x2.f32 %0, %1, %2;" : "=r"(p23) : "f"(v.w), "f"(v.z));
        out[i] = make_uint2(p01, p23);
    }
}

// ---------------------------------------------------------------------------
// fp16 HMMA GEMM body (NT), cp.async 4-stage pipeline, 512 threads (16 warps,
// 4m x 4n). BM=BN=128, BK=32, warp tile 32x32. Stage = 2 fp16 tiles,
// row stride 80B (conflict-free ldmatrix). wait_group 2 keeps 3 in flight.
// ---------------------------------------------------------------------------
#define ROWB 80
#define TILE_B (128 * ROWB)           // 10240 bytes per tile
#define STAGE_B (2 * TILE_B)          // 20480 bytes per stage
#define NSTAGE 4
#define GEMM_SMEM (NSTAGE * STAGE_B)  // 81920 bytes
#define NCH (D_ / 32)                 // 32 chunks

template <int SIG>
__device__ __forceinline__ void gemm_body(
    const __half* __restrict__ A, const __half* __restrict__ W,
    const float* __restrict__ bias, float* __restrict__ C, char* dsm)
{
    const uint32_t s0 = smem_u32(dsm);

    const int t    = threadIdx.x;
    const int warp = t >> 5;
    const int lane = t & 31;
    const int bm   = blockIdx.y * 128;
    const int bn   = blockIdx.x * 128;
    const int wm   = (warp & 3) * 32;
    const int wn   = (warp >> 2) * 32;

    const int crow = t >> 2;
    const int cseg = t & 3;
    const __half* gA = A + (size_t)(bm + crow) * D_ + cseg * 8;
    const __half* gW = W + (size_t)(bn + crow) * D_ + cseg * 8;
    const uint32_t cdst = (uint32_t)crow * ROWB + cseg * 16;

    const uint32_t a_off = (uint32_t)(wm + (lane & 15)) * ROWB + ((lane >> 4) << 4);
    const uint32_t w_off =
        (uint32_t)(wn + ((lane >> 4) << 3) + (lane & 7)) * ROWB + (((lane >> 3) & 1) << 4);

    float acc[2][4][4];
#pragma unroll
    for (int mt = 0; mt < 2; mt++)
#pragma unroll
        for (int nt = 0; nt < 4; nt++)
#pragma unroll
            for (int i = 0; i < 4; i++) acc[mt][nt][i] = 0.f;

#pragma unroll
    for (int st = 0; st < NSTAGE - 1; st++) {
        const uint32_t sb = s0 + st * STAGE_B;
        CP_ASYNC16(sb + cdst,          gA + st * 32);
        CP_ASYNC16(sb + TILE_B + cdst, gW + st * 32);
        CP_COMMIT();
    }

#pragma unroll 1
    for (int ch = 0; ch < NCH; ch++) {
        CP_WAIT2();
        __syncthreads();

        if (ch + NSTAGE - 1 < NCH) {
            const uint32_t sb = s0 + (uint32_t)((ch + NSTAGE - 1) & (NSTAGE - 1)) * STAGE_B;
            CP_ASYNC16(sb + cdst,          gA + (ch + NSTAGE - 1) * 32);
            CP_ASYNC16(sb + TILE_B + cdst, gW + (ch + NSTAGE - 1) * 32);
        }
        CP_COMMIT();

        const uint32_t cur = s0 + (uint32_t)(ch & (NSTAGE - 1)) * STAGE_B;
        const uint32_t cA = cur, cW = cur + TILE_B;

#pragma unroll
        for (int ks = 0; ks < 2; ks++) {
            const uint32_t ko = ks * 32;
            uint32_t av[2][4], wv[2][4];
            LDSM4(av[0], cA + a_off + ko);
            LDSM4(av[1], cA + a_off + 16 * ROWB + ko);
            LDSM4(wv[0], cW + w_off + ko);
            LDSM4(wv[1], cW + w_off + 16 * ROWB + ko);
#pragma unroll
            for (int mt = 0; mt < 2; mt++)
#pragma unroll
                for (int nt = 0; nt < 4; nt++)
                    MMA16816F16(acc[mt][nt], av[mt], (&wv[nt >> 1][(nt & 1) * 2]));
        }
    }

    const int er0 = bm + wm + (lane >> 2);
    const int ec0 = bn + wn + (lane & 3) * 2;

    float2 bb[4];
#pragma unroll
    for (int nt = 0; nt < 4; nt++)
        bb[nt] = *(const float2*)&bias[ec0 + nt * 8];

#pragma unroll
    for (int mt = 0; mt < 2; mt++) {
#pragma unroll
        for (int nt = 0; nt < 4; nt++) {
#pragma unroll
            for (int h = 0; h < 2; h++) {
                float2 v;
                v.x = acc[mt][nt][h * 2 + 0] + bb[nt].x;
                v.y = acc[mt][nt][h * 2 + 1] + bb[nt].y;
                if (SIG) {
                    v.x = 1.f / (1.f + __expf(-v.x));
                    v.y = 1.f / (1.f + __expf(-v.y));
                }
                *(float2*)(C + (size_t)(er0 + mt * 16 + h * 8) * D_ + ec0 + nt * 8) = v;
            }
        }
    }
}

// Merged Q/K/V projection: gridDim.z selects the triple
struct GemmTriple { const __half* A; const __half* W; const float* bias; float* C; };
struct GemmArgs   { GemmTriple t[3]; };

__global__ void __launch_bounds__(512) gemm_qkv(GemmArgs args)
{
    extern __shared__ __align__(128) char dsm[];
    const GemmTriple& tr = args.t[blockIdx.z];
    gemm_body<0>(tr.A, tr.W, tr.bias, tr.C, dsm);
}

__global__ void __launch_bounds__(512) gemm_o(
    const __half* __restrict__ A, const __half* __restrict__ W,
    const float* __restrict__ bias, float* __restrict__ C)
{
    extern __shared__ __align__(128) char dsm[];
    gemm_body<1>(A, W, bias, C, dsm);
}

// ---------------------------------------------------------------------------
// Cluster-pair attention. 2 CTAs per s (cluster dims 2), 256 threads each,
// CTA rank r owns batches 4r..4r+3. smem per CTA = 100 KB -> 2 CTAs/SM.
// Batch-softmax denominator partials exchanged via DSMEM (mapa + ld).
// smem floats: ES4[0..17408) = 4 batches x 64x68 exp-scores;
//              R[17408..25600): QK in pass1 (4x1024 Q | 4x1024 K),
//              then P (denominator strip, 64x68) then V (4x1088).
// ---------------------------------------------------------------------------
#define ES_STRIDE 68
#define ES_PER_B  (64 * ES_STRIDE)           // 4352
#define VS_PER_B  (16 * ES_STRIDE)           // 1088
#define ATTN_FLOATS (4 * ES_PER_B + 8192)    // 25600 floats = 100 KB
#define ATTN_SMEM (ATTN_FLOATS * 4)

__global__ void __launch_bounds__(256) __cluster_dims__(2, 1, 1) attn_kernel()
{
    extern __shared__ float smf[];
    float* ES = smf;
    float* R  = smf + 4 * ES_PER_B;

    const int s = blockIdx.x >> 1;
    const int t = threadIdx.x;
    uint32_t rank;
    asm("mov.u32 %0, %%cluster_ctarank;" : "=r"(rank));
    const int b0 = (int)rank * 4;

    // Load Q,K rows for this CTA's 4 batches (coalesced float4)
    for (int f = t; f < 4 * 256; f += 256) {
        const int bl = f >> 8;
        const int d4 = f & 255;
        const size_t g = ((size_t)(b0 + bl) * S_ + s) * 256 + d4;
        ((float4*)R)[f]          = ((const float4*)g_Q)[g];
        ((float4*)(R + 4096))[f] = ((const float4*)g_K)[g];
    }
    __syncthreads();

    const int tp = (t >> 4) * 4;
    const int tq = (t & 15) * 4;

    float sacc[4][4];
#pragma unroll
    for (int i = 0; i < 4; i++)
#pragma unroll
        for (int j = 0; j < 4; j++) sacc[i][j] = 0.f;

    // Pass 1: exp-scores for local 4 batches, partial batch-denominators
#pragma unroll
    for (int bl = 0; bl < 4; bl++) {
        const float* Qb = R + bl * 1024;
        const float* Kb = R + 4096 + bl * 1024;
        float acc[4][4];
#pragma unroll
        for (int i = 0; i < 4; i++)
#pragma unroll
            for (int j = 0; j < 4; j++) acc[i][j] = 0.f;

#pragma unroll
        for (int h = 0; h < 16; h++) {
            float4 q4 = *(const float4*)(Qb + h * 64 + tp);
            float4 k4 = *(const float4*)(Kb + h * 64 + tq);
            float qa[4] = {q4.x, q4.y, q4.z, q4.w};
            float ka[4] = {k4.x, k4.y, k4.z, k4.w};
#pragma unroll
            for (int i = 0; i < 4; i++)
#pragma unroll
                for (int j = 0; j < 4; j++)
                    acc[i][j] += qa[i] * ka[j];
        }
        float* ESb = ES + bl * ES_PER_B;
#pragma unroll
        for (int i = 0; i < 4; i++) {
            float4 e;
            e.x = __expf(acc[i][0] * 0.125f);
            e.y = __expf(acc[i][1] * 0.125f);
            e.z = __expf(acc[i][2] * 0.125f);
            e.w = __expf(acc[i][3] * 0.125f);
            sacc[i][0] += e.x; sacc[i][1] += e.y;
            sacc[i][2] += e.z; sacc[i][3] += e.w;
            *(float4*)&ESb[(tp + i) * ES_STRIDE + tq] = e;
        }
    }
    __syncthreads();   // Q/K reads done; R reusable as P strip

    // Write local partial denominators to P (= R base)
    float* P = R;
#pragma unroll
    for (int i = 0; i < 4; i++)
        *(float4*)&P[(tp + i) * ES_STRIDE + tq] =
            make_float4(sacc[i][0], sacc[i][1], sacc[i][2], sacc[i][3]);
    __syncthreads();

    CLUSTER_SYNC();    // both CTAs' P strips complete

    // Read peer partials via DSMEM, combine
    const uint32_t peer = rank ^ 1u;
    const uint32_t Pbase = smem_u32(P);
    float rd[4][4];
#pragma unroll
    for (int i = 0; i < 4; i++) {
#pragma unroll
        for (int j = 0; j < 4; j++) {
            uint32_t la = Pbase + (uint32_t)(((tp + i) * ES_STRIDE + tq + j) * 4);
            float pv = ld_dsmem(mapa_peer(la, peer));
            rd[i][j] = 1.f / (sacc[i][j] + pv);
        }
    }

    CLUSTER_SYNC();    // peer done reading OUR P -> safe to recycle R

    // Normalize local ES in place
#pragma unroll
    for (int bl = 0; bl < 4; bl++) {
        float* ESb = ES + bl * ES_PER_B;
#pragma unroll
        for (int i = 0; i < 4; i++) {
            float4 e = *(const float4*)&ESb[(tp + i) * ES_STRIDE + tq];
            e.x *= rd[i][0]; e.y *= rd[i][1];
            e.z *= rd[i][2]; e.w *= rd[i][3];
            *(float4*)&ESb[(tp + i) * ES_STRIDE + tq] = e;
        }
    }

    // Load V for local 4 batches (stride-68 padded at R base)
    for (int f = t; f < 4 * 256; f += 256) {
        const int bl = f >> 8;
        const int d4 = f & 255;
        const size_t g = ((size_t)(b0 + bl) * S_ + s) * 256 + d4;
        float4 v = ((const float4*)g_V)[g];
        const int d = d4 * 4;
        const int h = d >> 6;
        const int q = d & 63;
        float* Vb = R + bl * VS_PER_B + h * ES_STRIDE + q;
        Vb[0] = v.x; Vb[1] = v.y; Vb[2] = v.z; Vb[3] = v.w;
    }
    __syncthreads();

    // Pass 2 register-tiled: 64 threads per local b, 4h x 4p outputs each.
    {
        const int bl = t >> 6;
        const int u  = t & 63;
        const int lp = u & 15;
        const int lh = u >> 4;
        const float* ESb = ES + bl * ES_PER_B;
        const float* Vb  = R + bl * VS_PER_B;

        float oacc[4][4];
#pragma unroll
        for (int i = 0; i < 4; i++)
#pragma unroll
            for (int j = 0; j < 4; j++) oacc[i][j] = 0.f;

#pragma unroll
        for (int q = 0; q < 64; q += 4) {
            float4 e4[4], v4[4];
#pragma unroll
            for (int pp = 0; pp < 4; pp++)
                e4[pp] = *(const float4*)&ESb[(lp + 16 * pp) * ES_STRIDE + q];
#pragma unroll
            for (int hh = 0; hh < 4; hh++)
                v4[hh] = *(const float4*)&Vb[(lh + 4 * hh) * ES_STRIDE + q];
#pragma unroll
            for (int hh = 0; hh < 4; hh++)
#pragma unroll
                for (int pp = 0; pp < 4; pp++)
                    oacc[hh][pp] += e4[pp].x * v4[hh].x + e4[pp].y * v4[hh].y +
                                    e4[pp].z * v4[hh].z + e4[pp].w * v4[hh].w;
        }

        __half* ob = g_a16 + ((size_t)(b0 + bl) * S_ + s) * D_;
#pragma unroll
        for (int hh = 0; hh < 4; hh++)
#pragma unroll
            for (int pp = 0; pp < 4; pp++)
                ob[(lh + 4 * hh) * 64 + lp + 16 * pp] = __float2half(oacc[hh][pp]);
    }
}

// ---------------------------------------------------------------------------
extern "C" void kernel_launch(void* const* d_in, const int* in_sizes, int n_in,
                              void* d_out, int out_size)
{
    const float* query = (const float*)d_in[0];
    const float* key   = (const float*)d_in[1];
    const float* value = (const float*)d_in[2];
    const float* Wq    = (const float*)d_in[3];
    const float* bq    = (const float*)d_in[4];
    const float* Wk    = (const float*)d_in[5];
    const float* bk    = (const float*)d_in[6];
    const float* Wv    = (const float*)d_in[7];
    const float* bv    = (const float*)d_in[8];
    const float* Wo    = (const float*)d_in[9];
    const float* bo    = (const float*)d_in[10];
    float* out = (float*)d_out;

    float *gQ, *gK, *gV;
    __half *q16, *k16, *v16, *a16, *wq16, *wk16, *wv16, *wo16;
    cudaGetSymbolAddress((void**)&gQ, g_Q);
    cudaGetSymbolAddress((void**)&gK, g_K);
    cudaGetSymbolAddress((void**)&gV, g_V);
    cudaGetSymbolAddress((void**)&q16, g_q16);
    cudaGetSymbolAddress((void**)&k16, g_k16);
    cudaGetSymbolAddress((void**)&v16, g_v16);
    cudaGetSymbolAddress((void**)&a16, g_a16);
    cudaGetSymbolAddress((void**)&wq16, g_wq16);
    cudaGetSymbolAddress((void**)&wk16, g_wk16);
    cudaGetSymbolAddress((void**)&wv16, g_wv16);
    cudaGetSymbolAddress((void**)&wo16, g_wo16);

    // Fused pre-conversion: 3 inputs in one launch, 4 weights in another
    const int nIn4 = (M_TOT * D_) / 4;    // 2,097,152
    const int nW4  = (D_ * D_) / 4;       // 262,144
    {
        CvtArgs a{};
        a.in[0] = (const float4*)query; a.out[0] = (uint2*)q16;
        a.in[1] = (const float4*)key;   a.out[1] = (uint2*)k16;
        a.in[2] = (const float4*)value; a.out[2] = (uint2*)v16;
        dim3 g((nIn4 + 255) / 256, 1, 3);
        cvt_multi<<<g, 256>>>(a, nIn4);
    }
    {
        CvtArgs a{};
        a.in[0] = (const float4*)Wq; a.out[0] = (uint2*)wq16;
        a.in[1] = (const float4*)Wk; a.out[1] = (uint2*)wk16;
        a.in[2] = (const float4*)Wv; a.out[2] = (uint2*)wv16;
        a.in[3] = (const float4*)Wo; a.out[3] = (uint2*)wo16;
        dim3 g((nW4 + 255) / 256, 1, 4);
        cvt_multi<<<g, 256>>>(a, nW4);
    }

    cudaFuncSetAttribute(gemm_qkv,
                         cudaFuncAttributeMaxDynamicSharedMemorySize, GEMM_SMEM);
    cudaFuncSetAttribute(gemm_o,
                         cudaFuncAttributeMaxDynamicSharedMemorySize, GEMM_SMEM);
    cudaFuncSetAttribute(attn_kernel,
                         cudaFuncAttributeMaxDynamicSharedMemorySize, ATTN_SMEM);

    // Merged Q/K/V projection: z selects the triple (1536 CTAs, 10.4 waves)
    {
        GemmArgs args;
        args.t[0] = {q16, wq16, bq, gQ};
        args.t[1] = {k16, wk16, bk, gK};
        args.t[2] = {v16, wv16, bv, gV};
        dim3 grid(D_ / 128, M_TOT / 128, 3);   // (8, 64, 3)
        gemm_qkv<<<grid, 512, GEMM_SMEM>>>(args);
    }

    // Cluster-pair attention (2048 CTAs, cluster size 2 via __cluster_dims__)
    attn_kernel<<<2048, 256, ATTN_SMEM>>>();

    // Output projection + sigmoid
    {
        dim3 grid(D_ / 128, M_TOT / 128);      // (8, 64)
        gemm_o<<<grid, 512, GEMM_SMEM>>>(a16, wo16, bo, out);
    }
}